// round 5
// baseline (speedup 1.0000x reference)
#include <cuda_runtime.h>
#include <math.h>

#define L 1024
#define DD 192
#define BSZ 4
#define KK 4
#define NST 16

// ---------------- scratch (no allocs allowed) ----------------
__device__ float  g_xz[BSZ*2*DD*L];     // in_proj output: [0,192)=xx(pre-conv), [192,384)=z raw
__device__ float  g_xs[BSZ*KK*DD*L];    // conv+silu+cross-scan result
__device__ float  g_xdbl[BSZ*KK*38*L];  // x_proj output: rows 0..5 dt_rank, 6..21 B, 22..37 C
__device__ float  g_y[BSZ*KK*DD*L];     // scan output
__device__ float  g_merged[BSZ*DD*L];
__device__ double g_stats[2*BSZ];

__device__ __forceinline__ float siluf(float x){ return x / (1.0f + __expf(-x)); }

// ---------------- generic small SGEMM ----------------
__global__ void sgemm_kernel(const float* __restrict__ W, const float* __restrict__ X,
                             float* __restrict__ Y, int M, int Kc,
                             int wPerG, int wsel, int xPerG, int yPerG)
{
    __shared__ float As[8][32];
    __shared__ float Bs[8][128];
    int g = blockIdx.z;
    const float* Wg = W + (g % wsel) * wPerG;
    const float* Xg = X + g * xPerG;
    float*       Yg = Y + g * yPerG;
    int m0 = blockIdx.y * 32;
    int n0 = blockIdx.x * 128;
    int tid = threadIdx.x;
    int tx = tid & 31, ty = tid >> 5;

    float acc[4][4];
#pragma unroll
    for (int i = 0; i < 4; i++)
#pragma unroll
        for (int j = 0; j < 4; j++) acc[i][j] = 0.f;

    int ntiles = Kc >> 3;
    for (int kt = 0; kt < ntiles; kt++) {
        int m = m0 + tx;
        As[ty][tx] = (m < M) ? Wg[m * Kc + kt * 8 + ty] : 0.f;
        const float4* src = (const float4*)(Xg + (kt * 8 + ty) * L + n0);
        ((float4*)&Bs[ty][0])[tx] = src[tx];
        __syncthreads();
#pragma unroll
        for (int q = 0; q < 8; q++) {
            float a0 = As[q][ty*4+0], a1 = As[q][ty*4+1], a2 = As[q][ty*4+2], a3 = As[q][ty*4+3];
            float4 b4 = ((const float4*)&Bs[q][0])[tx];
            acc[0][0] = fmaf(a0,b4.x,acc[0][0]); acc[0][1] = fmaf(a0,b4.y,acc[0][1]);
            acc[0][2] = fmaf(a0,b4.z,acc[0][2]); acc[0][3] = fmaf(a0,b4.w,acc[0][3]);
            acc[1][0] = fmaf(a1,b4.x,acc[1][0]); acc[1][1] = fmaf(a1,b4.y,acc[1][1]);
            acc[1][2] = fmaf(a1,b4.z,acc[1][2]); acc[1][3] = fmaf(a1,b4.w,acc[1][3]);
            acc[2][0] = fmaf(a2,b4.x,acc[2][0]); acc[2][1] = fmaf(a2,b4.y,acc[2][1]);
            acc[2][2] = fmaf(a2,b4.z,acc[2][2]); acc[2][3] = fmaf(a2,b4.w,acc[2][3]);
            acc[3][0] = fmaf(a3,b4.x,acc[3][0]); acc[3][1] = fmaf(a3,b4.y,acc[3][1]);
            acc[3][2] = fmaf(a3,b4.z,acc[3][2]); acc[3][3] = fmaf(a3,b4.w,acc[3][3]);
        }
        __syncthreads();
    }
#pragma unroll
    for (int i = 0; i < 4; i++) {
        int m = m0 + ty * 4 + i;
        if (m < M) {
            float4 v = make_float4(acc[i][0], acc[i][1], acc[i][2], acc[i][3]);
            ((float4*)(Yg + m * L + n0))[tx] = v;
        }
    }
}

// ---------------- fused depthwise conv + silu + cross-scan scatter ----------------
__global__ void conv_scan_kernel(const float* __restrict__ cw, const float* __restrict__ cb)
{
    if (blockIdx.x == 0 && threadIdx.x < 2 * BSZ) g_stats[threadIdx.x] = 0.0;
    int t = blockIdx.x * blockDim.x + threadIdx.x;
    if (t >= BSZ * DD * L) return;
    int l = t & (L - 1);
    int d = (t >> 10) % DD;
    int b = (t >> 10) / DD;
    int i = l >> 5, j = l & 31;
    const float* src = g_xz + (b * 2 * DD + d) * L;
    float acc = cb[d];
#pragma unroll
    for (int u = 0; u < 3; u++) {
        int r = i + u - 1;
        if ((unsigned)r < 32u) {
#pragma unroll
            for (int v = 0; v < 3; v++) {
                int c = j + v - 1;
                if ((unsigned)c < 32u)
                    acc = fmaf(cw[d * 9 + u * 3 + v], src[r * 32 + c], acc);
            }
        }
    }
    float val = siluf(acc);
    int l0 = (j << 5)        + (((j & 1) == 0) ? i : 31 - i);
    int l1 = ((31 - j) << 5) + ((j & 1) ? 31 - i : i);
    int l2 = (i << 5)        + (((i & 1) == 0) ? j : 31 - j);
    int l3 = ((31 - i) << 5) + ((i & 1) ? 31 - j : j);
    float* base = g_xs + ((b * 4) * DD + d) * L;
    base[l0]               = val;
    base[DD * L + l1]      = val;
    base[2 * DD * L + l2]  = val;
    base[3 * DD * L + l3]  = val;
}

// ---------------- chunked selective scan ----------------
// block = 256 threads = 2 d x 8 chunks x 16 n. chunk = 128 steps.
// grid = 16 bk * 96 dpairs = 1536 blocks.
__global__ void __launch_bounds__(256, 4)
scan_kernel(const float* __restrict__ A_logs, const float* __restrict__ Ds,
            const float* __restrict__ dt_w, const float* __restrict__ dt_b)
{
    __shared__ float sDel[2][L];
    __shared__ float sDu[2][L];
    __shared__ float sPbuf[2][8][16][17];
    __shared__ float sHloc[2][8][16];
    __shared__ float sPp[2][8][16];
    __shared__ float sHst[2][8][16];

    int blk = blockIdx.x;
    int d0  = (blk % 96) * 2;
    int bk  = blk / 96;           // b*4+k
    int k   = bk & 3;
    int tid = threadIdx.x;
    int n   = tid & 15;
    int c   = (tid >> 4) & 7;
    int di  = tid >> 7;
    int d   = d0 + di;
    int kd  = k * DD + d;

    const float* XdP = g_xdbl + (bk * 38) * L;
    const float* BP  = g_xdbl + (bk * 38 + 6)  * L;
    const float* CP  = g_xdbl + (bk * 38 + 22) * L;
    const float* uP  = g_xs   + (bk * DD) * L;
    float*       yP  = g_y    + (bk * DD) * L;

    // ---- phase A: delta projection + softplus + du, once per (d,t) ----
    for (int idx = tid; idx < 2 * L; idx += 256) {
        int dj = idx >> 10;         // 0/1
        int t  = idx & (L - 1);
        int kdr = k * DD + d0 + dj;
        float acc = dt_b[kdr];
#pragma unroll
        for (int q = 0; q < 6; q++)
            acc = fmaf(XdP[q * L + t], dt_w[kdr * 6 + q], acc);
        float del = (acc > 20.f) ? acc : __logf(1.f + __expf(acc));
        sDel[dj][idx & (L - 1)] = del;
        sDu[dj][idx & (L - 1)]  = del * uP[(d0 + dj) * L + t];
    }
    float Areg = -__expf(A_logs[kd * NST + n]);
    float Dreg = Ds[kd];
    __syncthreads();

    int tbase = c * 128;
    const float4* del4 = (const float4*)(&sDel[di][tbase]);
    const float4* du4  = (const float4*)(&sDu[di][tbase]);
    const float4* B4   = (const float4*)(BP + n * L + tbase);
    const float4* C4   = (const float4*)(CP + n * L + tbase);

    // ---- pass 1: local scan from h=0, track prefix product ----
    {
        float h = 0.f, P = 1.f;
#pragma unroll 8
        for (int g = 0; g < 32; g++) {
            float4 dl = del4[g], du = du4[g], b4 = B4[g];
            float a;
            a = __expf(dl.x * Areg); h = fmaf(a, h, du.x * b4.x); P *= a;
            a = __expf(dl.y * Areg); h = fmaf(a, h, du.y * b4.y); P *= a;
            a = __expf(dl.z * Areg); h = fmaf(a, h, du.z * b4.z); P *= a;
            a = __expf(dl.w * Areg); h = fmaf(a, h, du.w * b4.w); P *= a;
        }
        sHloc[di][c][n] = h;
        sPp[di][c][n]   = P;
    }
    __syncthreads();

    // ---- combine: serial scan over 8 chunk summaries (32 threads) ----
    if (tid < 32) {
        int dj = tid >> 4, nn = tid & 15;
        float hs = 0.f;
#pragma unroll
        for (int cc = 0; cc < 8; cc++) {
            sHst[dj][cc][nn] = hs;
            hs = fmaf(sPp[dj][cc][nn], hs, sHloc[dj][cc][nn]);
        }
    }
    __syncthreads();

    // ---- pass 2: replay with correct h_start, reduce over n, write y ----
    {
        float h = sHst[di][c][n];
#pragma unroll 2
        for (int s16 = 0; s16 < 8; s16++) {
#pragma unroll
            for (int g = 0; g < 4; g++) {
                int gg = s16 * 4 + g;
                float4 dl = del4[gg], du = du4[gg], b4 = B4[gg], c4 = C4[gg];
                float a;
                a = __expf(dl.x * Areg); h = fmaf(a, h, du.x * b4.x); sPbuf[di][c][n][g*4+0] = h * c4.x;
                a = __expf(dl.y * Areg); h = fmaf(a, h, du.y * b4.y); sPbuf[di][c][n][g*4+1] = h * c4.y;
                a = __expf(dl.z * Areg); h = fmaf(a, h, du.z * b4.z); sPbuf[di][c][n][g*4+2] = h * c4.z;
                a = __expf(dl.w * Areg); h = fmaf(a, h, du.w * b4.w); sPbuf[di][c][n][g*4+3] = h * c4.w;
            }
            __syncwarp();
            float sum = 0.f;
#pragma unroll
            for (int q = 0; q < 16; q++) sum += sPbuf[di][c][q][n];
            int tt = tbase + s16 * 16 + n;
            float ut = uP[d * L + tt];
            yP[d * L + tt] = fmaf(Dreg, ut, sum);
            __syncwarp();
        }
    }
}

// ---------------- cross merge + layernorm stats ----------------
__global__ void merge_kernel()
{
    int b = blockIdx.y;
    int t = blockIdx.x * 256 + threadIdx.x;
    int l = t & (L - 1);
    int d = t >> 10;
    int i = l >> 5, j = l & 31;
    int l0 = (j << 5)        + (((j & 1) == 0) ? i : 31 - i);
    int l1 = ((31 - j) << 5) + ((j & 1) ? 31 - i : i);
    int l2 = (i << 5)        + (((i & 1) == 0) ? j : 31 - j);
    int l3 = ((31 - i) << 5) + ((i & 1) ? 31 - j : j);
    const float* yb = g_y + ((b * 4) * DD + d) * L;
    float m = yb[l0] + yb[DD * L + l1] + yb[2 * DD * L + l2] + yb[3 * DD * L + l3];
    g_merged[(b * DD + d) * L + l] = m;

    __shared__ float s1[256], s2[256];
    int tx = threadIdx.x;
    s1[tx] = m;
    s2[tx] = m * m;
    __syncthreads();
    for (int s = 128; s > 0; s >>= 1) {
        if (tx < s) { s1[tx] += s1[tx + s]; s2[tx] += s2[tx + s]; }
        __syncthreads();
    }
    if (tx == 0) {
        atomicAdd(&g_stats[2 * b],     (double)s1[0]);
        atomicAdd(&g_stats[2 * b + 1], (double)s2[0]);
    }
}

// ---------------- out_proj GEMM with fused normalize + gate prologue ----------------
__global__ void outproj_kernel(const float* __restrict__ W, float* __restrict__ out,
                               const float* __restrict__ gamma, const float* __restrict__ beta)
{
    __shared__ float As[8][32];
    __shared__ float Bs[8][128];
    int g = blockIdx.z;
    double Ninv = 1.0 / (double)(DD * L);
    double mu_d = g_stats[2 * g] * Ninv;
    double var_d = g_stats[2 * g + 1] * Ninv - mu_d * mu_d;
    float mu  = (float)mu_d;
    float inv = rsqrtf((float)var_d + 1e-6f);

    int m0 = blockIdx.y * 32;
    int n0 = blockIdx.x * 128;
    int tid = threadIdx.x;
    int tx = tid & 31, ty = tid >> 5;

    float acc[4][4];
#pragma unroll
    for (int i = 0; i < 4; i++)
#pragma unroll
        for (int j = 0; j < 4; j++) acc[i][j] = 0.f;

    for (int kt = 0; kt < 24; kt++) {
        int m = m0 + tx;
        As[ty][tx] = W[m * DD + kt * 8 + ty];
        int dd = kt * 8 + ty;
        float ga = gamma[dd] * inv;
        float c0 = beta[dd] - mu * ga;
        const float4* mg = (const float4*)(g_merged + (g * DD + dd) * L + n0);
        const float4* zp = (const float4*)(g_xz + (g * 2 * DD + DD + dd) * L + n0);
        float4 m4 = mg[tx];
        float4 z4 = zp[tx];
        float4 r;
        r.x = fmaf(m4.x, ga, c0) * siluf(z4.x);
        r.y = fmaf(m4.y, ga, c0) * siluf(z4.y);
        r.z = fmaf(m4.z, ga, c0) * siluf(z4.z);
        r.w = fmaf(m4.w, ga, c0) * siluf(z4.w);
        ((float4*)&Bs[ty][0])[tx] = r;
        __syncthreads();
#pragma unroll
        for (int q = 0; q < 8; q++) {
            float a0 = As[q][ty*4+0], a1 = As[q][ty*4+1], a2 = As[q][ty*4+2], a3 = As[q][ty*4+3];
            float4 b4 = ((const float4*)&Bs[q][0])[tx];
            acc[0][0] = fmaf(a0,b4.x,acc[0][0]); acc[0][1] = fmaf(a0,b4.y,acc[0][1]);
            acc[0][2] = fmaf(a0,b4.z,acc[0][2]); acc[0][3] = fmaf(a0,b4.w,acc[0][3]);
            acc[1][0] = fmaf(a1,b4.x,acc[1][0]); acc[1][1] = fmaf(a1,b4.y,acc[1][1]);
            acc[1][2] = fmaf(a1,b4.z,acc[1][2]); acc[1][3] = fmaf(a1,b4.w,acc[1][3]);
            acc[2][0] = fmaf(a2,b4.x,acc[2][0]); acc[2][1] = fmaf(a2,b4.y,acc[2][1]);
            acc[2][2] = fmaf(a2,b4.z,acc[2][2]); acc[2][3] = fmaf(a2,b4.w,acc[2][3]);
            acc[3][0] = fmaf(a3,b4.x,acc[3][0]); acc[3][1] = fmaf(a3,b4.y,acc[3][1]);
            acc[3][2] = fmaf(a3,b4.z,acc[3][2]); acc[3][3] = fmaf(a3,b4.w,acc[3][3]);
        }
        __syncthreads();
    }
#pragma unroll
    for (int i = 0; i < 4; i++) {
        int m = m0 + ty * 4 + i;
        float4 v = make_float4(acc[i][0], acc[i][1], acc[i][2], acc[i][3]);
        ((float4*)(out + (g * 96 + m) * L + n0))[tx] = v;
    }
}

// ---------------- host launch ----------------
extern "C" void kernel_launch(void* const* d_in, const int* in_sizes, int n_in,
                              void* d_out, int out_size)
{
    const float* x        = (const float*)d_in[0];
    const float* in_proj  = (const float*)d_in[1];
    const float* conv_w   = (const float*)d_in[2];
    const float* conv_b   = (const float*)d_in[3];
    const float* x_proj_w = (const float*)d_in[4];
    const float* dt_w     = (const float*)d_in[5];
    const float* dt_b     = (const float*)d_in[6];
    const float* A_logs   = (const float*)d_in[7];
    const float* Ds       = (const float*)d_in[8];
    const float* gamma    = (const float*)d_in[9];
    const float* beta     = (const float*)d_in[10];
    const float* out_proj = (const float*)d_in[11];
    float* out = (float*)d_out;

    void *p_xz, *p_xs, *p_xdbl;
    cudaGetSymbolAddress(&p_xz,   g_xz);
    cudaGetSymbolAddress(&p_xs,   g_xs);
    cudaGetSymbolAddress(&p_xdbl, g_xdbl);

    sgemm_kernel<<<dim3(8, 12, 4), 256>>>(in_proj, x, (float*)p_xz,
                                          384, 96, 0, 1, 96 * L, 384 * L);
    conv_scan_kernel<<<(BSZ * DD * L) / 256, 256>>>(conv_w, conv_b);
    sgemm_kernel<<<dim3(8, 2, 16), 256>>>(x_proj_w, (const float*)p_xs, (float*)p_xdbl,
                                          38, 192, 38 * 192, 4, 192 * L, 38 * L);
    scan_kernel<<<1536, 256>>>(A_logs, Ds, dt_w, dt_b);
    merge_kernel<<<dim3((DD * L) / 256, BSZ), 256>>>();
    outproj_kernel<<<dim3(8, 3, 4), 256>>>(out_proj, out, gamma, beta);
    (void)in_sizes; (void)n_in; (void)out_size;
}

// round 6
// speedup vs baseline: 1.5792x; 1.5792x over previous
#include <cuda_runtime.h>
#include <math.h>

#define L 1024
#define DD 192
#define BSZ 4
#define KK 4
#define NST 16

// ---------------- scratch (no allocs allowed) ----------------
__device__ float  g_xz[BSZ*2*DD*L];     // in_proj output: [0,192)=xx(pre-conv), [192,384)=z raw
__device__ float  g_xs[BSZ*KK*DD*L];    // conv+silu+cross-scan result
__device__ float  g_xdbl[BSZ*KK*38*L];  // x_proj output: rows 0..5 dt_rank used (B/C go transposed)
__device__ float  g_Bt[BSZ*KK*L*NST];   // B transposed: [bk][l][n]
__device__ float  g_Ct[BSZ*KK*L*NST];   // C transposed: [bk][l][n]
__device__ float  g_y[BSZ*KK*DD*L];     // scan output
__device__ float  g_merged[BSZ*DD*L];
__device__ double g_stats[2*BSZ];

__device__ __forceinline__ float siluf(float x){ return x / (1.0f + __expf(-x)); }

// ---------------- generic small SGEMM (in_proj) ----------------
__global__ void sgemm_kernel(const float* __restrict__ W, const float* __restrict__ X,
                             float* __restrict__ Y, int M, int Kc,
                             int wPerG, int wsel, int xPerG, int yPerG)
{
    __shared__ float As[8][32];
    __shared__ float Bs[8][128];
    int g = blockIdx.z;
    const float* Wg = W + (g % wsel) * wPerG;
    const float* Xg = X + g * xPerG;
    float*       Yg = Y + g * yPerG;
    int m0 = blockIdx.y * 32;
    int n0 = blockIdx.x * 128;
    int tid = threadIdx.x;
    int tx = tid & 31, ty = tid >> 5;

    float acc[4][4];
#pragma unroll
    for (int i = 0; i < 4; i++)
#pragma unroll
        for (int j = 0; j < 4; j++) acc[i][j] = 0.f;

    int ntiles = Kc >> 3;
    for (int kt = 0; kt < ntiles; kt++) {
        int m = m0 + tx;
        As[ty][tx] = (m < M) ? Wg[m * Kc + kt * 8 + ty] : 0.f;
        const float4* src = (const float4*)(Xg + (kt * 8 + ty) * L + n0);
        ((float4*)&Bs[ty][0])[tx] = src[tx];
        __syncthreads();
#pragma unroll
        for (int q = 0; q < 8; q++) {
            float a0 = As[q][ty*4+0], a1 = As[q][ty*4+1], a2 = As[q][ty*4+2], a3 = As[q][ty*4+3];
            float4 b4 = ((const float4*)&Bs[q][0])[tx];
            acc[0][0] = fmaf(a0,b4.x,acc[0][0]); acc[0][1] = fmaf(a0,b4.y,acc[0][1]);
            acc[0][2] = fmaf(a0,b4.z,acc[0][2]); acc[0][3] = fmaf(a0,b4.w,acc[0][3]);
            acc[1][0] = fmaf(a1,b4.x,acc[1][0]); acc[1][1] = fmaf(a1,b4.y,acc[1][1]);
            acc[1][2] = fmaf(a1,b4.z,acc[1][2]); acc[1][3] = fmaf(a1,b4.w,acc[1][3]);
            acc[2][0] = fmaf(a2,b4.x,acc[2][0]); acc[2][1] = fmaf(a2,b4.y,acc[2][1]);
            acc[2][2] = fmaf(a2,b4.z,acc[2][2]); acc[2][3] = fmaf(a2,b4.w,acc[2][3]);
            acc[3][0] = fmaf(a3,b4.x,acc[3][0]); acc[3][1] = fmaf(a3,b4.y,acc[3][1]);
            acc[3][2] = fmaf(a3,b4.z,acc[3][2]); acc[3][3] = fmaf(a3,b4.w,acc[3][3]);
        }
        __syncthreads();
    }
#pragma unroll
    for (int i = 0; i < 4; i++) {
        int m = m0 + ty * 4 + i;
        if (m < M) {
            float4 v = make_float4(acc[i][0], acc[i][1], acc[i][2], acc[i][3]);
            ((float4*)(Yg + m * L + n0))[tx] = v;
        }
    }
}

// ---------------- x_proj SGEMM: rows 0-5 normal, B/C rows written transposed ----------------
__global__ void xproj_kernel(const float* __restrict__ W, const float* __restrict__ X)
{
    __shared__ float As[8][32];
    __shared__ float Bs[8][128];
    int g = blockIdx.z;                 // bk
    const float* Wg = W + (g & 3) * (38 * DD);
    const float* Xg = X + g * DD * L;
    float*       Yg = g_xdbl + g * 38 * L;
    int m0 = blockIdx.y * 32;
    int n0 = blockIdx.x * 128;
    int tid = threadIdx.x;
    int tx = tid & 31, ty = tid >> 5;

    float acc[4][4];
#pragma unroll
    for (int i = 0; i < 4; i++)
#pragma unroll
        for (int j = 0; j < 4; j++) acc[i][j] = 0.f;

    for (int kt = 0; kt < 24; kt++) {
        int m = m0 + tx;
        As[ty][tx] = (m < 38) ? Wg[m * DD + kt * 8 + ty] : 0.f;
        const float4* src = (const float4*)(Xg + (kt * 8 + ty) * L + n0);
        ((float4*)&Bs[ty][0])[tx] = src[tx];
        __syncthreads();
#pragma unroll
        for (int q = 0; q < 8; q++) {
            float a0 = As[q][ty*4+0], a1 = As[q][ty*4+1], a2 = As[q][ty*4+2], a3 = As[q][ty*4+3];
            float4 b4 = ((const float4*)&Bs[q][0])[tx];
            acc[0][0] = fmaf(a0,b4.x,acc[0][0]); acc[0][1] = fmaf(a0,b4.y,acc[0][1]);
            acc[0][2] = fmaf(a0,b4.z,acc[0][2]); acc[0][3] = fmaf(a0,b4.w,acc[0][3]);
            acc[1][0] = fmaf(a1,b4.x,acc[1][0]); acc[1][1] = fmaf(a1,b4.y,acc[1][1]);
            acc[1][2] = fmaf(a1,b4.z,acc[1][2]); acc[1][3] = fmaf(a1,b4.w,acc[1][3]);
            acc[2][0] = fmaf(a2,b4.x,acc[2][0]); acc[2][1] = fmaf(a2,b4.y,acc[2][1]);
            acc[2][2] = fmaf(a2,b4.z,acc[2][2]); acc[2][3] = fmaf(a2,b4.w,acc[2][3]);
            acc[3][0] = fmaf(a3,b4.x,acc[3][0]); acc[3][1] = fmaf(a3,b4.y,acc[3][1]);
            acc[3][2] = fmaf(a3,b4.z,acc[3][2]); acc[3][3] = fmaf(a3,b4.w,acc[3][3]);
        }
        __syncthreads();
    }
#pragma unroll
    for (int i = 0; i < 4; i++) {
        int m = m0 + ty * 4 + i;
        if (m < 38) {
            if (m < 6) {
                float4 v = make_float4(acc[i][0], acc[i][1], acc[i][2], acc[i][3]);
                ((float4*)(Yg + m * L + n0))[tx] = v;
            } else {
                float* dst = (m < 22) ? (g_Bt + g * L * NST + (m - 6))
                                      : (g_Ct + g * L * NST + (m - 22));
                int lb = n0 + tx * 4;
                dst[(lb + 0) * NST] = acc[i][0];
                dst[(lb + 1) * NST] = acc[i][1];
                dst[(lb + 2) * NST] = acc[i][2];
                dst[(lb + 3) * NST] = acc[i][3];
            }
        }
    }
}

// ---------------- fused depthwise conv + silu + cross-scan scatter ----------------
__global__ void conv_scan_kernel(const float* __restrict__ cw, const float* __restrict__ cb)
{
    if (blockIdx.x == 0 && threadIdx.x < 2 * BSZ) g_stats[threadIdx.x] = 0.0;
    int t = blockIdx.x * blockDim.x + threadIdx.x;
    if (t >= BSZ * DD * L) return;
    int l = t & (L - 1);
    int d = (t >> 10) % DD;
    int b = (t >> 10) / DD;
    int i = l >> 5, j = l & 31;
    const float* src = g_xz + (b * 2 * DD + d) * L;
    float acc = cb[d];
#pragma unroll
    for (int u = 0; u < 3; u++) {
        int r = i + u - 1;
        if ((unsigned)r < 32u) {
#pragma unroll
            for (int v = 0; v < 3; v++) {
                int c = j + v - 1;
                if ((unsigned)c < 32u)
                    acc = fmaf(cw[d * 9 + u * 3 + v], src[r * 32 + c], acc);
            }
        }
    }
    float val = siluf(acc);
    int l0 = (j << 5)        + (((j & 1) == 0) ? i : 31 - i);
    int l1 = ((31 - j) << 5) + ((j & 1) ? 31 - i : i);
    int l2 = (i << 5)        + (((i & 1) == 0) ? j : 31 - j);
    int l3 = ((31 - i) << 5) + ((i & 1) ? 31 - j : j);
    float* base = g_xs + ((b * 4) * DD + d) * L;
    base[l0]               = val;
    base[DD * L + l1]      = val;
    base[2 * DD * L + l2]  = val;
    base[3 * DD * L + l3]  = val;
}

// ---------------- chunked selective scan (n-contiguous B/C) ----------------
// block = 256 threads = 2 d x 8 chunks x 16 n. chunk = 128 steps.
// grid = 16 bk * 96 dpairs = 1536 blocks.
__global__ void __launch_bounds__(256, 4)
scan_kernel(const float* __restrict__ A_logs, const float* __restrict__ Ds,
            const float* __restrict__ dt_w, const float* __restrict__ dt_b)
{
    __shared__ float sDel[2][L];
    __shared__ float sDu[2][L];
    __shared__ float sPbuf[2][8][16][17];
    __shared__ float sHloc[2][8][16];
    __shared__ float sPp[2][8][16];
    __shared__ float sHst[2][8][16];

    int blk = blockIdx.x;
    int d0  = (blk % 96) * 2;
    int bk  = blk / 96;
    int k   = bk & 3;
    int tid = threadIdx.x;
    int n   = tid & 15;
    int c   = (tid >> 4) & 7;
    int di  = tid >> 7;
    int d   = d0 + di;
    int kd  = k * DD + d;

    const float* XdP = g_xdbl + (bk * 38) * L;
    const float* uP  = g_xs   + (bk * DD) * L;
    float*       yP  = g_y    + (bk * DD) * L;

    // ---- phase A: delta projection + softplus + du, once per (d,t) ----
    for (int idx = tid; idx < 2 * L; idx += 256) {
        int dj = idx >> 10;
        int t  = idx & (L - 1);
        int kdr = k * DD + d0 + dj;
        float acc = dt_b[kdr];
#pragma unroll
        for (int q = 0; q < 6; q++)
            acc = fmaf(XdP[q * L + t], dt_w[kdr * 6 + q], acc);
        float del = (acc > 20.f) ? acc : __logf(1.f + __expf(acc));
        sDel[dj][t] = del;
        sDu[dj][t]  = del * uP[(d0 + dj) * L + t];
    }
    float Areg = -__expf(A_logs[kd * NST + n]);
    float Dreg = Ds[kd];
    __syncthreads();

    int tbase = c * 128;
    const float4* del4 = (const float4*)(&sDel[di][tbase]);
    const float4* du4  = (const float4*)(&sDu[di][tbase]);
    const float* bp = g_Bt + bk * L * NST + tbase * NST + n;
    const float* cp = g_Ct + bk * L * NST + tbase * NST + n;

    // ---- pass 1: local scan from h=0, track prefix product ----
    {
        float h = 0.f, P = 1.f;
#pragma unroll 4
        for (int g = 0; g < 32; g++) {
            float4 dl = del4[g], du = du4[g];
            float b0 = bp[(g*4+0)*NST], b1 = bp[(g*4+1)*NST],
                  b2 = bp[(g*4+2)*NST], b3 = bp[(g*4+3)*NST];
            float a;
            a = __expf(dl.x * Areg); h = fmaf(a, h, du.x * b0); P *= a;
            a = __expf(dl.y * Areg); h = fmaf(a, h, du.y * b1); P *= a;
            a = __expf(dl.z * Areg); h = fmaf(a, h, du.z * b2); P *= a;
            a = __expf(dl.w * Areg); h = fmaf(a, h, du.w * b3); P *= a;
        }
        sHloc[di][c][n] = h;
        sPp[di][c][n]   = P;
    }
    __syncthreads();

    // ---- combine: serial scan over 8 chunk summaries ----
    if (tid < 32) {
        int dj = tid >> 4, nn = tid & 15;
        float hs = 0.f;
#pragma unroll
        for (int cc = 0; cc < 8; cc++) {
            sHst[dj][cc][nn] = hs;
            hs = fmaf(sPp[dj][cc][nn], hs, sHloc[dj][cc][nn]);
        }
    }
    __syncthreads();

    // ---- pass 2: replay with correct h_start, reduce over n, write y ----
    {
        float h = sHst[di][c][n];
#pragma unroll 2
        for (int s16 = 0; s16 < 8; s16++) {
#pragma unroll
            for (int g = 0; g < 4; g++) {
                int gg = s16 * 4 + g;
                float4 dl = del4[gg], du = du4[gg];
                float b0 = bp[(gg*4+0)*NST], b1 = bp[(gg*4+1)*NST],
                      b2 = bp[(gg*4+2)*NST], b3 = bp[(gg*4+3)*NST];
                float c0 = cp[(gg*4+0)*NST], c1 = cp[(gg*4+1)*NST],
                      c2 = cp[(gg*4+2)*NST], c3 = cp[(gg*4+3)*NST];
                float a;
                a = __expf(dl.x * Areg); h = fmaf(a, h, du.x * b0); sPbuf[di][c][n][g*4+0] = h * c0;
                a = __expf(dl.y * Areg); h = fmaf(a, h, du.y * b1); sPbuf[di][c][n][g*4+1] = h * c1;
                a = __expf(dl.z * Areg); h = fmaf(a, h, du.z * b2); sPbuf[di][c][n][g*4+2] = h * c2;
                a = __expf(dl.w * Areg); h = fmaf(a, h, du.w * b3); sPbuf[di][c][n][g*4+3] = h * c3;
            }
            __syncwarp();
            float sum = 0.f;
#pragma unroll
            for (int q = 0; q < 16; q++) sum += sPbuf[di][c][q][n];
            int tt = tbase + s16 * 16 + n;
            float ut = uP[d * L + tt];
            yP[d * L + tt] = fmaf(Dreg, ut, sum);
            __syncwarp();
        }
    }
}

// ---------------- cross merge + layernorm stats ----------------
__global__ void merge_kernel()
{
    int b = blockIdx.y;
    int t = blockIdx.x * 256 + threadIdx.x;
    int l = t & (L - 1);
    int d = t >> 10;
    int i = l >> 5, j = l & 31;
    int l0 = (j << 5)        + (((j & 1) == 0) ? i : 31 - i);
    int l1 = ((31 - j) << 5) + ((j & 1) ? 31 - i : i);
    int l2 = (i << 5)        + (((i & 1) == 0) ? j : 31 - j);
    int l3 = ((31 - i) << 5) + ((i & 1) ? 31 - j : j);
    const float* yb = g_y + ((b * 4) * DD + d) * L;
    float m = yb[l0] + yb[DD * L + l1] + yb[2 * DD * L + l2] + yb[3 * DD * L + l3];
    g_merged[(b * DD + d) * L + l] = m;

    __shared__ float s1[256], s2[256];
    int tx = threadIdx.x;
    s1[tx] = m;
    s2[tx] = m * m;
    __syncthreads();
    for (int s = 128; s > 0; s >>= 1) {
        if (tx < s) { s1[tx] += s1[tx + s]; s2[tx] += s2[tx + s]; }
        __syncthreads();
    }
    if (tx == 0) {
        atomicAdd(&g_stats[2 * b],     (double)s1[0]);
        atomicAdd(&g_stats[2 * b + 1], (double)s2[0]);
    }
}

// ---------------- out_proj GEMM with fused normalize + gate prologue ----------------
__global__ void outproj_kernel(const float* __restrict__ W, float* __restrict__ out,
                               const float* __restrict__ gamma, const float* __restrict__ beta)
{
    __shared__ float As[8][32];
    __shared__ float Bs[8][128];
    int g = blockIdx.z;
    double Ninv = 1.0 / (double)(DD * L);
    double mu_d = g_stats[2 * g] * Ninv;
    double var_d = g_stats[2 * g + 1] * Ninv - mu_d * mu_d;
    float mu  = (float)mu_d;
    float inv = rsqrtf((float)var_d + 1e-6f);

    int m0 = blockIdx.y * 32;
    int n0 = blockIdx.x * 128;
    int tid = threadIdx.x;
    int tx = tid & 31, ty = tid >> 5;

    float acc[4][4];
#pragma unroll
    for (int i = 0; i < 4; i++)
#pragma unroll
        for (int j = 0; j < 4; j++) acc[i][j] = 0.f;

    for (int kt = 0; kt < 24; kt++) {
        int m = m0 + tx;
        As[ty][tx] = W[m * DD + kt * 8 + ty];
        int dd = kt * 8 + ty;
        float ga = gamma[dd] * inv;
        float c0 = beta[dd] - mu * ga;
        const float4* mg = (const float4*)(g_merged + (g * DD + dd) * L + n0);
        const float4* zp = (const float4*)(g_xz + (g * 2 * DD + DD + dd) * L + n0);
        float4 m4 = mg[tx];
        float4 z4 = zp[tx];
        float4 r;
        r.x = fmaf(m4.x, ga, c0) * siluf(z4.x);
        r.y = fmaf(m4.y, ga, c0) * siluf(z4.y);
        r.z = fmaf(m4.z, ga, c0) * siluf(z4.z);
        r.w = fmaf(m4.w, ga, c0) * siluf(z4.w);
        ((float4*)&Bs[ty][0])[tx] = r;
        __syncthreads();
#pragma unroll
        for (int q = 0; q < 8; q++) {
            float a0 = As[q][ty*4+0], a1 = As[q][ty*4+1], a2 = As[q][ty*4+2], a3 = As[q][ty*4+3];
            float4 b4 = ((const float4*)&Bs[q][0])[tx];
            acc[0][0] = fmaf(a0,b4.x,acc[0][0]); acc[0][1] = fmaf(a0,b4.y,acc[0][1]);
            acc[0][2] = fmaf(a0,b4.z,acc[0][2]); acc[0][3] = fmaf(a0,b4.w,acc[0][3]);
            acc[1][0] = fmaf(a1,b4.x,acc[1][0]); acc[1][1] = fmaf(a1,b4.y,acc[1][1]);
            acc[1][2] = fmaf(a1,b4.z,acc[1][2]); acc[1][3] = fmaf(a1,b4.w,acc[1][3]);
            acc[2][0] = fmaf(a2,b4.x,acc[2][0]); acc[2][1] = fmaf(a2,b4.y,acc[2][1]);
            acc[2][2] = fmaf(a2,b4.z,acc[2][2]); acc[2][3] = fmaf(a2,b4.w,acc[2][3]);
            acc[3][0] = fmaf(a3,b4.x,acc[3][0]); acc[3][1] = fmaf(a3,b4.y,acc[3][1]);
            acc[3][2] = fmaf(a3,b4.z,acc[3][2]); acc[3][3] = fmaf(a3,b4.w,acc[3][3]);
        }
        __syncthreads();
    }
#pragma unroll
    for (int i = 0; i < 4; i++) {
        int m = m0 + ty * 4 + i;
        float4 v = make_float4(acc[i][0], acc[i][1], acc[i][2], acc[i][3]);
        ((float4*)(out + (g * 96 + m) * L + n0))[tx] = v;
    }
}

// ---------------- host launch ----------------
extern "C" void kernel_launch(void* const* d_in, const int* in_sizes, int n_in,
                              void* d_out, int out_size)
{
    const float* x        = (const float*)d_in[0];
    const float* in_proj  = (const float*)d_in[1];
    const float* conv_w   = (const float*)d_in[2];
    const float* conv_b   = (const float*)d_in[3];
    const float* x_proj_w = (const float*)d_in[4];
    const float* dt_w     = (const float*)d_in[5];
    const float* dt_b     = (const float*)d_in[6];
    const float* A_logs   = (const float*)d_in[7];
    const float* Ds       = (const float*)d_in[8];
    const float* gamma    = (const float*)d_in[9];
    const float* beta     = (const float*)d_in[10];
    const float* out_proj = (const float*)d_in[11];
    float* out = (float*)d_out;

    void *p_xz, *p_xs;
    cudaGetSymbolAddress(&p_xz, g_xz);
    cudaGetSymbolAddress(&p_xs, g_xs);

    sgemm_kernel<<<dim3(8, 12, 4), 256>>>(in_proj, x, (float*)p_xz,
                                          384, 96, 0, 1, 96 * L, 384 * L);
    conv_scan_kernel<<<(BSZ * DD * L) / 256, 256>>>(conv_w, conv_b);
    xproj_kernel<<<dim3(8, 2, 16), 256>>>(x_proj_w, (const float*)p_xs);
    scan_kernel<<<1536, 256>>>(A_logs, Ds, dt_w, dt_b);
    merge_kernel<<<dim3((DD * L) / 256, BSZ), 256>>>();
    outproj_kernel<<<dim3(8, 3, 4), 256>>>(out_proj, out, gamma, beta);
    (void)in_sizes; (void)n_in; (void)out_size;
}